// round 1
// baseline (speedup 1.0000x reference)
#include <cuda_runtime.h>
#include <math.h>
#include <stdint.h>

#define LL 50
#define NA 120
#define SS 100
#define RQ 64        // padded rec row (float2 units)
#define FSLOTS 73    // padded f slots for M (8 left pad + 50 data + 15 right pad)

// ---------------- device global scratch (no allocation allowed) ----------------
__device__ float2 g_rec[8][LL][LL];          // conv(receptor), channels interleaved
__device__ float2 g_lig[8][LL][LL];          // conv(ligand)
__device__ float2 g_M[NA][8][LL][LL];        // weight-folded rotated ligand, ch-interleaved
__device__ float  g_bv[NA * 8];
__device__ int    g_bi[NA * 8];

// ---------------- kernel 1: 3x3 SAME conv (cross-correlation) + bias ----------------
__global__ void conv_kernel(const float* __restrict__ rec, const float* __restrict__ lig,
                            const float* __restrict__ cw, const float* __restrict__ cb) {
    int b = blockIdx.x, which = blockIdx.y;
    const float* x = (which == 0 ? rec : lig) + b * (LL * LL);
    float w0[9], w1[9];
#pragma unroll
    for (int k = 0; k < 9; k++) { w0[k] = cw[k]; w1[k] = cw[9 + k]; }
    float b0 = cb[0], b1 = cb[1];
    for (int idx = threadIdx.x; idx < LL * LL; idx += blockDim.x) {
        int h = idx / LL, w = idx % LL;
        float s0 = b0, s1 = b1;
#pragma unroll
        for (int kh = 0; kh < 3; kh++) {
            int hh = h + kh - 1;
            if (hh < 0 || hh >= LL) continue;
#pragma unroll
            for (int kw = 0; kw < 3; kw++) {
                int ww = w + kw - 1;
                if (ww < 0 || ww >= LL) continue;
                float v = x[hh * LL + ww];
                s0 += v * w0[kh * 3 + kw];
                s1 += v * w1[kh * 3 + kw];
            }
        }
        if (which == 0) g_rec[b][h][w] = make_float2(s0, s1);
        else            g_lig[b][h][w] = make_float2(s0, s1);
    }
}

// ---------------- kernel 2: bilinear rotation + scorer-weight folding ----------------
// M_i[a,b] = sum_j scorer_w[2i+j] * rotate(lig_feat_j, angle_a)
__global__ void rot_kernel(const float* __restrict__ sw) {
    int b = blockIdx.x, a = blockIdx.y;
    float ang = (float)a * 0.026179938779914946f;   // pi/120
    float cs = cosf(ang), sn = sinf(ang);
    float sw0 = sw[0], sw1 = sw[1], sw2 = sw[2], sw3 = sw[3];
    for (int idx = threadIdx.x; idx < LL * LL; idx += blockDim.x) {
        int r = idx / LL, c = idx % LL;
        float gx = -1.0f + (float)c * (2.0f / 49.0f);
        float gy = -1.0f + (float)r * (2.0f / 49.0f);
        float xr =  cs * gx + sn * gy;
        float yr = -sn * gx + cs * gy;
        float ix = (xr + 1.0f) * 0.5f * 49.0f;
        float iy = (yr + 1.0f) * 0.5f * 49.0f;
        float x0 = floorf(ix), y0 = floorf(iy);
        float s0 = 0.f, s1 = 0.f;
#pragma unroll
        for (int t = 0; t < 4; t++) {           // (dx,dy) = (0,0),(1,0),(0,1),(1,1)
            float xc = x0 + (float)(t & 1);
            float yc = y0 + (float)(t >> 1);
            float wgt = (1.0f - fabsf(ix - xc)) * (1.0f - fabsf(iy - yc));
            bool valid = (xc >= 0.f) && (xc < 50.f) && (yc >= 0.f) && (yc < 50.f);
            int xi = min(max((int)xc, 0), 49);
            int yi = min(max((int)yc, 0), 49);
            float2 v = g_lig[b][yi][xi];
            float wv = valid ? wgt : 0.f;
            s0 += v.x * wv;
            s1 += v.y * wv;
        }
        g_M[a][b][r][c] = make_float2(sw0 * s0 + sw1 * s1, sw2 * s0 + sw3 * s1);
    }
}

// ---------------- kernel 3: spatial cross-correlation + block argmax ----------------
// score(sx,sy) = sum_ch sum_{p,q} rec[p][q] * M[p-sx][q-sy],  sx=u-50, sy=v-50
// SMEM: rec2[50][64] (q zero-padded), M2[FSLOTS][50] transposed (f-slot major, zero-padded)
extern __shared__ float2 sm2[];

__global__ void __launch_bounds__(256) corr_kernel() {
    int b = blockIdx.x, a = blockIdx.y;
    float2* rec2 = sm2;                 // 50*RQ float2
    float2* M2   = sm2 + LL * RQ;       // FSLOTS*50 float2
    int tid = threadIdx.x;

    // zero everything (padding), then fill
    for (int i = tid; i < LL * RQ + FSLOTS * LL; i += 256) sm2[i] = make_float2(0.f, 0.f);
    __syncthreads();
    for (int i = tid; i < LL * LL; i += 256) {
        int p = i / LL, q = i % LL;
        rec2[p * RQ + q]        = g_rec[b][p][q];
        M2[(q + 8) * LL + p]    = g_M[a][b][p][q];   // transposed: [f=q+8][prow=p]
    }
    __syncthreads();

    int lane = tid & 31, warp = tid >> 5;
    float bestv = -INFINITY; int besti = 0;

    const unsigned long long* recU = reinterpret_cast<const unsigned long long*>(rec2);
    const unsigned long long* mU   = reinterpret_cast<const unsigned long long*>(M2);

    for (int it = warp; it < 52; it += 8) {
        int ug = it / 13;           // u-group 0..3
        int vs = it % 13;           // v-strip 0..12
        int u = ug * 32 + lane;     // output row (u < 100 valid)
        int sx = u - LL;
        int sy0 = vs * 8 - LL;
        int qlo = max(0, sy0);
        int qhi = min(LL, sy0 + 57);
        int qpad = (qhi - qlo + 7) & ~7;
        int f0 = qlo - sy0;         // >= 0
        bool uvalid = (u < SS);
        int plo = max(0, sx), phi = min(LL, LL + sx);

        unsigned long long acc[8];
#pragma unroll
        for (int vi = 0; vi < 8; vi++) acc[vi] = 0ull;

        if (uvalid && phi > plo) {
            for (int p = 0; p < LL; p++) {
                if (p < plo || p >= phi) continue;
                int prow = p - sx;
                const unsigned long long* mcol = mU + prow;
                const unsigned long long* rrow = recU + p * RQ + qlo;
                unsigned long long wv[8];
#pragma unroll
                for (int j = 1; j < 8; j++) wv[j] = mcol[(f0 + j) * LL];
                wv[0] = 0ull;
                int fb = (f0 + 8) * LL;
                for (int t = 0; t < qpad; t += 8) {
#pragma unroll
                    for (int tt = 0; tt < 8; tt++) {
                        unsigned long long a2 = rrow[t + tt];
                        wv[tt] = mcol[fb + (t + tt) * LL];
#pragma unroll
                        for (int vi = 0; vi < 8; vi++) {
                            asm("fma.rn.f32x2 %0, %1, %2, %0;"
                                : "+l"(acc[vi])
                                : "l"(a2), "l"(wv[(tt - vi) & 7]));
                        }
                    }
                }
            }
        }
        // fold this strip into running best
#pragma unroll
        for (int vi = 0; vi < 8; vi++) {
            int v = vs * 8 + vi;
            if (uvalid && v < SS) {
                float lo = __uint_as_float((unsigned)(acc[vi] & 0xffffffffull));
                float hi = __uint_as_float((unsigned)(acc[vi] >> 32));
                float s = lo + hi;
                int idx = u * SS + v;
                if (s > bestv || (s == bestv && idx < besti)) { bestv = s; besti = idx; }
            }
        }
    }

    // block-level argmax reduction (reuse smem as scratch)
    __syncthreads();
    float* sv = (float*)sm2;
    int*   si = (int*)(sv + 256);
    sv[tid] = bestv; si[tid] = besti;
    __syncthreads();
    for (int s2 = 128; s2 > 0; s2 >>= 1) {
        if (tid < s2) {
            float ov = sv[tid + s2]; int oi = si[tid + s2];
            if (ov > sv[tid] || (ov == sv[tid] && oi < si[tid])) { sv[tid] = ov; si[tid] = oi; }
        }
        __syncthreads();
    }
    if (tid == 0) { g_bv[a * 8 + b] = sv[0]; g_bi[a * 8 + b] = si[0]; }
}

// ---------------- kernel 4: final per-batch argmax over angles + emit ----------------
__global__ void final_kernel(float* __restrict__ out) {
    int warp = threadIdx.x >> 5, lane = threadIdx.x & 31;
    if (warp >= 8) return;
    int b = warp;
    float bv = -INFINITY; int bi = 0x7fffffff;
    for (int a = lane; a < NA; a += 32) {
        float v = g_bv[a * 8 + b];
        int idx = a * (SS * SS) + g_bi[a * 8 + b];
        if (v > bv || (v == bv && idx < bi)) { bv = v; bi = idx; }
    }
#pragma unroll
    for (int o = 16; o > 0; o >>= 1) {
        float ov = __shfl_down_sync(0xffffffffu, bv, o);
        int   oi = __shfl_down_sync(0xffffffffu, bi, o);
        if (ov > bv || (ov == bv && oi < bi)) { bv = ov; bi = oi; }
    }
    if (lane == 0) {
        int a = bi / (SS * SS);
        int r = bi % (SS * SS);
        int x = r / SS;
        int y = r % SS;
        out[b]             = (float)a * 0.026179938779914946f;   // best angle
        out[8 + 2 * b]     = (float)(x - LL);                    // trans x
        out[8 + 2 * b + 1] = (float)(y - LL);                    // trans y
    }
}

// ---------------- launch ----------------
extern "C" void kernel_launch(void* const* d_in, const int* in_sizes, int n_in,
                              void* d_out, int out_size) {
    const float* rec = (const float*)d_in[0];
    const float* lig = (const float*)d_in[1];
    const float* cw  = (const float*)d_in[2];
    const float* cb  = (const float*)d_in[3];
    const float* sw  = (const float*)d_in[4];
    // d_in[5] = scorer_b: constant shift, never affects argmax -> unused

    const int smem_bytes = (LL * RQ + FSLOTS * LL) * (int)sizeof(float2);  // 54800
    cudaFuncSetAttribute(corr_kernel, cudaFuncAttributeMaxDynamicSharedMemorySize, smem_bytes);

    conv_kernel <<<dim3(8, 2),  256>>>(rec, lig, cw, cb);
    rot_kernel  <<<dim3(8, NA), 256>>>(sw);
    corr_kernel <<<dim3(8, NA), 256, smem_bytes>>>();
    final_kernel<<<1, 256>>>((float*)d_out);
}